// round 1
// baseline (speedup 1.0000x reference)
#include <cuda_runtime.h>
#include <cuda_bf16.h>

#define NN 100000
#define NE 400000
#define NG 4096
#define BN_EPS 1e-5f

// ---------------- scratch (device globals; no allocations allowed) ----------------
__device__ float g_Y[NN * 256];        // projection output
__device__ float g_A[NN * 256];        // self + bias + aggregated neighbors
__device__ float g_H1[NN * 256];
__device__ float g_H2[NN * 128];
__device__ float g_H3[NN * 64];
__device__ float g_pool[NG * 64];
__device__ float g_stats[512];         // [0:256) col sums, [256:512) col sumsq
__device__ int   g_is64;

// ---------------- dtype detection (int64 vs int32 indices) ----------------
__global__ void detect_dtype(const unsigned int* __restrict__ w, int n) {
    __shared__ int anyNZ;
    if (threadIdx.x == 0) anyNZ = 0;
    __syncthreads();
    for (int i = threadIdx.x; i < n; i += blockDim.x)
        if (w[2 * i + 1] != 0u) anyNZ = 1;
    __syncthreads();
    if (threadIdx.x == 0) g_is64 = (anyNZ == 0) ? 1 : 0;
}

__device__ __forceinline__ int load_idx(const void* p, long long i, int is64) {
    return is64 ? (int)((const long long*)p)[i] : ((const int*)p)[i];
}

// ---------------- tiled fp32 SGEMM ----------------
// C[M,N] = op(A[M,K]) @ B[K,N]; optional reluIn on A, bias+reluOut on C,
// optional second output C2 = (pre-relu C value) + bias2 (used to init agg buffer).
template <int BM, int BN, int BK, int TM, int TN>
__global__ __launch_bounds__((BM / TM) * (BN / TN))
void sgemm(const float* __restrict__ A, const float* __restrict__ B,
           float* __restrict__ C, int M, int N, int K,
           const float* __restrict__ bias, int reluIn, int reluOut,
           float* __restrict__ C2, const float* __restrict__ bias2) {
    constexpr int NT = (BM / TM) * (BN / TN);
    __shared__ float As[BK][BM];
    __shared__ float Bs[BK][BN];
    const int tid = threadIdx.x;
    const int tx = tid % (BN / TN);
    const int ty = tid / (BN / TN);
    const int m0 = blockIdx.y * BM;
    const int n0 = blockIdx.x * BN;

    float acc[TM][TN];
#pragma unroll
    for (int i = 0; i < TM; i++)
#pragma unroll
        for (int j = 0; j < TN; j++) acc[i][j] = 0.f;

    for (int k0 = 0; k0 < K; k0 += BK) {
#pragma unroll
        for (int i = tid; i < BM * BK; i += NT) {
            int m = i / BK, k = i % BK;
            int gm = m0 + m, gk = k0 + k;
            float v = 0.f;
            if (gm < M && gk < K) v = A[(long long)gm * K + gk];
            if (reluIn) v = fmaxf(v, 0.f);
            As[k][m] = v;
        }
#pragma unroll
        for (int i = tid; i < BK * BN; i += NT) {
            int k = i / BN, n = i % BN;
            int gk = k0 + k;
            float v = 0.f;
            if (gk < K) v = B[(long long)gk * N + n0 + n];
            Bs[k][n] = v;
        }
        __syncthreads();
#pragma unroll
        for (int kk = 0; kk < BK; kk++) {
            const float4* a4 = (const float4*)&As[kk][ty * TM];
            const float4* b4 = (const float4*)&Bs[kk][tx * TN];
            float4 a0 = a4[0], a1 = a4[1];
            float4 b0 = b4[0];
            float a[TM] = {a0.x, a0.y, a0.z, a0.w, a1.x, a1.y, a1.z, a1.w};
            float b[TN] = {b0.x, b0.y, b0.z, b0.w};
#pragma unroll
            for (int i = 0; i < TM; i++)
#pragma unroll
                for (int j = 0; j < TN; j++) acc[i][j] = fmaf(a[i], b[j], acc[i][j]);
        }
        __syncthreads();
    }

    const int gn0 = n0 + tx * TN;
    float4 bv = make_float4(0.f, 0.f, 0.f, 0.f);
    if (bias) bv = *(const float4*)&bias[gn0];
    float4 bv2 = make_float4(0.f, 0.f, 0.f, 0.f);
    if (C2 && bias2) bv2 = *(const float4*)&bias2[gn0];

#pragma unroll
    for (int i = 0; i < TM; i++) {
        int gm = m0 + ty * TM + i;
        if (gm >= M) continue;
        float4 v = make_float4(acc[i][0], acc[i][1], acc[i][2], acc[i][3]);
        if (C2) {
            float4 w = make_float4(v.x + bv2.x, v.y + bv2.y, v.z + bv2.z, v.w + bv2.w);
            *(float4*)&C2[(long long)gm * N + gn0] = w;
        }
        v.x += bv.x; v.y += bv.y; v.z += bv.z; v.w += bv.w;
        if (reluOut) {
            v.x = fmaxf(v.x, 0.f); v.y = fmaxf(v.y, 0.f);
            v.z = fmaxf(v.z, 0.f); v.w = fmaxf(v.w, 0.f);
        }
        *(float4*)&C[(long long)gm * N + gn0] = v;
    }
}

// ---------------- edge scatter: A[dst] += Y[src] ----------------
__global__ void scatter_add(const float* __restrict__ Y, float* __restrict__ A,
                            const void* __restrict__ eidx, int E, int C4) {
    const int is64 = g_is64;
    long long i = (long long)blockIdx.x * blockDim.x + threadIdx.x;
    long long total = (long long)E * C4;
    if (i >= total) return;
    int e = (int)(i / C4);
    int c = (int)(i % C4) * 4;
    int C = C4 * 4;
    int src = load_idx(eidx, e, is64);
    int dst = load_idx(eidx, (long long)E + e, is64);
    float4 v = *(const float4*)&Y[(long long)src * C + c];
    float* p = &A[(long long)dst * C + c];
    atomicAdd(p + 0, v.x);
    atomicAdd(p + 1, v.y);
    atomicAdd(p + 2, v.z);
    atomicAdd(p + 3, v.w);
}

// ---------------- batchnorm statistics + apply ----------------
__global__ void zero_f(float* __restrict__ p, int n) {
    int i = blockIdx.x * blockDim.x + threadIdx.x;
    if (i < n) p[i] = 0.f;
}

__global__ void col_stats(const float* __restrict__ H, int M, int C) {
    const int c = threadIdx.x;            // blockDim.x == C
    const int r0 = blockIdx.x * 256;
    const int r1 = min(r0 + 256, M);
    float s = 0.f, q = 0.f;
    for (int r = r0; r < r1; ++r) {
        float v = H[(long long)r * C + c];
        s += v;
        q = fmaf(v, v, q);
    }
    atomicAdd(&g_stats[c], s);
    atomicAdd(&g_stats[256 + c], q);
}

__global__ void bn_apply(float* __restrict__ H, int M, int C,
                         const float* __restrict__ gam, const float* __restrict__ bet) {
    long long i = (long long)blockIdx.x * blockDim.x + threadIdx.x;
    long long total4 = (long long)M * (C / 4);
    if (i >= total4) return;
    int c = (int)(i % (C / 4)) * 4;
    float4 v = *(float4*)&H[i * 4];
    float invN = 1.f / (float)M;
    float* vp = &v.x;
#pragma unroll
    for (int j = 0; j < 4; j++) {
        float mu = g_stats[c + j] * invN;
        float var = fmaf(-mu, mu, g_stats[256 + c + j] * invN);
        float sc = rsqrtf(var + BN_EPS) * gam[c + j];
        vp[j] = fmaf(vp[j] - mu, sc, bet[c + j]);
    }
    *(float4*)&H[i * 4] = v;
}

// ---------------- pooling + head ----------------
__global__ void pool_add(const float* __restrict__ H, float* __restrict__ P,
                         const void* __restrict__ batch, int M) {
    const int is64 = g_is64;
    long long i = (long long)blockIdx.x * blockDim.x + threadIdx.x;
    long long total = (long long)M * 16;      // C=64 -> 16 float4 per node
    if (i >= total) return;
    int node = (int)(i / 16);
    int c = (int)(i % 16) * 4;
    int gph = load_idx(batch, node, is64);
    float4 v = *(const float4*)&H[(long long)node * 64 + c];
    float* p = &P[(long long)gph * 64 + c];
    atomicAdd(p + 0, v.x);
    atomicAdd(p + 1, v.y);
    atomicAdd(p + 2, v.z);
    atomicAdd(p + 3, v.w);
}

__global__ void head_kernel(const float* __restrict__ P,
                            const float* __restrict__ Wf1, const float* __restrict__ bf1,
                            const float* __restrict__ Wf2, const float* __restrict__ bf2,
                            float* __restrict__ out, int G) {
    int g = blockIdx.x * blockDim.x + threadIdx.x;
    if (g >= G) return;
    float acc[16];
#pragma unroll
    for (int j = 0; j < 16; j++) acc[j] = bf1[j];
    const float* p = &P[(long long)g * 64];
    for (int k = 0; k < 64; k++) {
        float pv = p[k];
#pragma unroll
        for (int j = 0; j < 16; j++) acc[j] = fmaf(pv, Wf1[k * 16 + j], acc[j]);
    }
    float o = bf2[0];
#pragma unroll
    for (int j = 0; j < 16; j++) o = fmaf(fmaxf(acc[j], 0.f), Wf2[j], o);
    out[g] = fmaxf(o, 0.f);
}

// ---------------- host launcher ----------------
static void launch_sgemm(const float* A, const float* B, float* C,
                         int M, int N, int K, const float* bias,
                         int reluIn, int reluOut, float* C2, const float* bias2) {
    dim3 grid(N / 64, (M + 127) / 128);
    sgemm<128, 64, 16, 8, 4><<<grid, 256>>>(A, B, C, M, N, K, bias, reluIn, reluOut, C2, bias2);
}

extern "C" void kernel_launch(void* const* d_in, const int* in_sizes, int n_in,
                              void* d_out, int out_size) {
    const float* x    = (const float*)d_in[0];
    const void*  eidx = d_in[1];
    const void*  batc = d_in[2];
    const float* W1a = (const float*)d_in[3];  const float* b1a = (const float*)d_in[4];
    const float* W1b = (const float*)d_in[5];  const float* b1b = (const float*)d_in[6];
    const float* g1  = (const float*)d_in[7];  const float* be1 = (const float*)d_in[8];
    const float* W2a = (const float*)d_in[9];  const float* b2a = (const float*)d_in[10];
    const float* W2b = (const float*)d_in[11]; const float* b2b = (const float*)d_in[12];
    const float* g2  = (const float*)d_in[13]; const float* be2 = (const float*)d_in[14];
    const float* W3a = (const float*)d_in[15]; const float* b3a = (const float*)d_in[16];
    const float* W3b = (const float*)d_in[17]; const float* b3b = (const float*)d_in[18];
    const float* g3  = (const float*)d_in[19]; const float* be3 = (const float*)d_in[20];
    const float* Wf1 = (const float*)d_in[21]; const float* bf1 = (const float*)d_in[22];
    const float* Wf2 = (const float*)d_in[23]; const float* bf2 = (const float*)d_in[24];

    float *Y, *A, *H1, *H2, *H3, *P, *ST;
    cudaGetSymbolAddress((void**)&Y,  g_Y);
    cudaGetSymbolAddress((void**)&A,  g_A);
    cudaGetSymbolAddress((void**)&H1, g_H1);
    cudaGetSymbolAddress((void**)&H2, g_H2);
    cudaGetSymbolAddress((void**)&H3, g_H3);
    cudaGetSymbolAddress((void**)&P,  g_pool);
    cudaGetSymbolAddress((void**)&ST, g_stats);

    detect_dtype<<<1, 256>>>((const unsigned int*)eidx, 1024);

    const int M = NN;
    // ---- Layer 1: in 373 -> mid 256 ----
    launch_sgemm(x, W1a, Y, M, 256, 373, nullptr, 0, 0, A, b1a);   // Y = x@W1a ; A = Y + b1a
    {
        long long tot = (long long)NE * 64;
        scatter_add<<<(int)((tot + 255) / 256), 256>>>(Y, A, eidx, NE, 64);
    }
    launch_sgemm(A, W1b, H1, M, 256, 256, b1b, 1, 1, nullptr, nullptr); // H1 = relu(relu(A)@W1b + b1b)
    zero_f<<<2, 256>>>(ST, 512);
    col_stats<<<(M + 255) / 256, 256>>>(H1, M, 256);
    {
        long long tot4 = (long long)M * 64;
        bn_apply<<<(int)((tot4 + 255) / 256), 256>>>(H1, M, 256, g1, be1);
    }

    // ---- Layer 2: in 256 -> mid 128 ----
    launch_sgemm(H1, W2a, Y, M, 128, 256, nullptr, 0, 0, A, b2a);
    {
        long long tot = (long long)NE * 32;
        scatter_add<<<(int)((tot + 255) / 256), 256>>>(Y, A, eidx, NE, 32);
    }
    launch_sgemm(A, W2b, H2, M, 128, 128, b2b, 1, 1, nullptr, nullptr);
    zero_f<<<2, 256>>>(ST, 512);
    col_stats<<<(M + 255) / 256, 128>>>(H2, M, 128);
    {
        long long tot4 = (long long)M * 32;
        bn_apply<<<(int)((tot4 + 255) / 256), 256>>>(H2, M, 128, g2, be2);
    }

    // ---- Layer 3: in 128 -> mid 64 ----
    launch_sgemm(H2, W3a, Y, M, 64, 128, nullptr, 0, 0, A, b3a);
    {
        long long tot = (long long)NE * 16;
        scatter_add<<<(int)((tot + 255) / 256), 256>>>(Y, A, eidx, NE, 16);
    }
    launch_sgemm(A, W3b, H3, M, 64, 64, b3b, 1, 1, nullptr, nullptr);
    zero_f<<<2, 256>>>(ST, 512);
    col_stats<<<(M + 255) / 256, 64>>>(H3, M, 64);
    {
        long long tot4 = (long long)M * 16;
        bn_apply<<<(int)((tot4 + 255) / 256), 256>>>(H3, M, 64, g3, be3);
    }

    // ---- Pool + head ----
    zero_f<<<(NG * 64 + 255) / 256, 256>>>(P, NG * 64);
    {
        long long tot = (long long)M * 16;
        pool_add<<<(int)((tot + 255) / 256), 256>>>(H3, P, batc, M);
    }
    head_kernel<<<(NG + 127) / 128, 128>>>(P, Wf1, bf1, Wf2, bf2, (float*)d_out, NG);
}

// round 5
// speedup vs baseline: 1.0997x; 1.0997x over previous
#include <cuda_runtime.h>
#include <cuda_bf16.h>
#include <cstdint>

#define NN 100000
#define NE 400000
#define NG 4096
#define BN_EPS 1e-5f

// ---------------- scratch (device globals; no allocations allowed) ----------------
__device__ float g_Y[NN * 256];        // projection output
__device__ float g_A[NN * 256];        // self + bias + aggregated neighbors
__device__ float g_H1[NN * 256];
__device__ float g_H2[NN * 128];
__device__ float g_H3[NN * 64];
__device__ float g_pool[NG * 64];
__device__ float g_stats[512];         // [0:256) col sums, [256:512) col sumsq
__device__ float g_Bt[373 * 256];      // transposed weight scratch [N,K]
__device__ int   g_is64;

// ---------------- dtype detection (int64 vs int32 indices) ----------------
__global__ void detect_dtype(const unsigned int* __restrict__ w, int n) {
    __shared__ int anyNZ;
    if (threadIdx.x == 0) anyNZ = 0;
    __syncthreads();
    for (int i = threadIdx.x; i < n; i += blockDim.x)
        if (w[2 * i + 1] != 0u) anyNZ = 1;
    __syncthreads();
    if (threadIdx.x == 0) g_is64 = (anyNZ == 0) ? 1 : 0;
}

__device__ __forceinline__ int load_idx(const void* p, long long i, int is64) {
    return is64 ? (int)((const long long*)p)[i] : ((const int*)p)[i];
}

__device__ __forceinline__ uint32_t f2tf32(float v) {
    uint32_t u;
    asm("cvt.rna.tf32.f32 %0, %1;" : "=r"(u) : "f"(v));
    return u;
}

// split v into hi (tf32) + lo (tf32 of residual); hi+lo ~ v to ~21 mantissa bits
__device__ __forceinline__ void split_tf32(float v, uint32_t& hi, uint32_t& lo) {
    hi = f2tf32(v);
    float r = v - __uint_as_float(hi);
    lo = f2tf32(r);
}

// ---------------- weight transpose: [K,N] -> [N,K] ----------------
__global__ void transpose_w(const float* __restrict__ in, float* __restrict__ out,
                            int K, int N) {
    __shared__ float t[32][33];
    int kx = blockIdx.y * 32, nx = blockIdx.x * 32;
    int x = threadIdx.x, y = threadIdx.y;      // 32 x 8
#pragma unroll
    for (int j = 0; j < 32; j += 8) {
        int k = kx + y + j, n = nx + x;
        t[y + j][x] = (k < K && n < N) ? in[(long long)k * N + n] : 0.f;
    }
    __syncthreads();
#pragma unroll
    for (int j = 0; j < 32; j += 8) {
        int n = nx + y + j, k = kx + x;
        if (n < N && k < K) out[(long long)n * K + k] = t[x][y + j];
    }
}

// ---------------- 3xTF32 mma.sync GEMM (fp32-accurate) ----------------
// C[M,N] = f(A[M,K]) @ Bt[N,K]^T  (f = optional relu on A)
// epilogue: C = (acc + bias) [relu]; optional C2 = acc + bias2.
template <int BN_, int WM_, int WN_>
__global__ __launch_bounds__(256)
void mma_gemm(const float* __restrict__ A, const float* __restrict__ Bt,
              float* __restrict__ C, int M, int N, int K,
              const float* __restrict__ bias, int reluIn, int reluOut,
              float* __restrict__ C2, const float* __restrict__ bias2) {
    constexpr int BM = 128, BK = 32, STR = 36;
    constexpr int MW = BM / WM_;
    constexpr int NW = BN_ / WN_;
    constexpr int MAT = MW / 16;
    constexpr int NAT = NW / 8;
    __shared__ float As[BM * STR];
    __shared__ float Bs[BN_ * STR];

    const int tid = threadIdx.x;
    const int wid = tid >> 5, lane = tid & 31;
    const int gid = lane >> 2, tig = lane & 3;
    const int wm = wid / WN_, wn = wid % WN_;
    const int m0 = blockIdx.y * BM;
    const int n0 = blockIdx.x * BN_;

    float acc[MAT][NAT][4];
#pragma unroll
    for (int i = 0; i < MAT; i++)
#pragma unroll
        for (int j = 0; j < NAT; j++)
#pragma unroll
            for (int q = 0; q < 4; q++) acc[i][j][q] = 0.f;

    const int KT = (K + BK - 1) / BK;
    for (int kt = 0; kt < KT; ++kt) {
        const int k0 = kt * BK;
        // stage A: 128 x 32, coalesced global, padded-stride STS (raw fp32)
#pragma unroll
        for (int it = 0; it < (BM * BK) / 256; ++it) {
            int i = tid + it * 256;
            int row = i >> 5, col = i & 31;
            int gm = m0 + row, gk = k0 + col;
            float v = 0.f;
            if (gm < M && gk < K) {
                v = A[(long long)gm * K + gk];
                if (reluIn) v = fmaxf(v, 0.f);
            }
            As[row * STR + col] = v;
        }
        // stage B: BN_ x 32 from Bt[N,K] (raw fp32)
#pragma unroll
        for (int it = 0; it < (BN_ * BK) / 256; ++it) {
            int i = tid + it * 256;
            int n = i >> 5, col = i & 31;
            int gn = n0 + n, gk = k0 + col;
            float v = 0.f;
            if (gn < N && gk < K) v = Bt[(long long)gn * K + gk];
            Bs[n * STR + col] = v;
        }
        __syncthreads();

#pragma unroll
        for (int ks = 0; ks < 4; ks++) {
            const int ac = ks * 8 + tig;
            uint32_t ah[MAT][4], al[MAT][4], bh[NAT][2], bl[NAT][2];
#pragma unroll
            for (int im = 0; im < MAT; im++) {
                int ar = wm * MW + im * 16 + gid;
                split_tf32(As[ar * STR + ac],       ah[im][0], al[im][0]);
                split_tf32(As[(ar + 8) * STR + ac], ah[im][1], al[im][1]);
                split_tf32(As[ar * STR + ac + 4],   ah[im][2], al[im][2]);
                split_tf32(As[(ar + 8) * STR + ac + 4], ah[im][3], al[im][3]);
            }
#pragma unroll
            for (int in = 0; in < NAT; in++) {
                int br = wn * NW + in * 8 + gid;
                split_tf32(Bs[br * STR + ac],     bh[in][0], bl[in][0]);
                split_tf32(Bs[br * STR + ac + 4], bh[in][1], bl[in][1]);
            }
#pragma unroll
            for (int im = 0; im < MAT; im++)
#pragma unroll
                for (int in = 0; in < NAT; in++) {
                    // acc += a_lo * b_hi
                    asm volatile(
                        "mma.sync.aligned.m16n8k8.row.col.f32.tf32.tf32.f32 "
                        "{%0,%1,%2,%3}, {%4,%5,%6,%7}, {%8,%9}, {%0,%1,%2,%3};"
                        : "+f"(acc[im][in][0]), "+f"(acc[im][in][1]),
                          "+f"(acc[im][in][2]), "+f"(acc[im][in][3])
                        : "r"(al[im][0]), "r"(al[im][1]), "r"(al[im][2]), "r"(al[im][3]),
                          "r"(bh[in][0]), "r"(bh[in][1]));
                    // acc += a_hi * b_lo
                    asm volatile(
                        "mma.sync.aligned.m16n8k8.row.col.f32.tf32.tf32.f32 "
                        "{%0,%1,%2,%3}, {%4,%5,%6,%7}, {%8,%9}, {%0,%1,%2,%3};"
                        : "+f"(acc[im][in][0]), "+f"(acc[im][in][1]),
                          "+f"(acc[im][in][2]), "+f"(acc[im][in][3])
                        : "r"(ah[im][0]), "r"(ah[im][1]), "r"(ah[im][2]), "r"(ah[im][3]),
                          "r"(bl[in][0]), "r"(bl[in][1]));
                    // acc += a_hi * b_hi
                    asm volatile(
                        "mma.sync.aligned.m16n8k8.row.col.f32.tf32.tf32.f32 "
                        "{%0,%1,%2,%3}, {%4,%5,%6,%7}, {%8,%9}, {%0,%1,%2,%3};"
                        : "+f"(acc[im][in][0]), "+f"(acc[im][in][1]),
                          "+f"(acc[im][in][2]), "+f"(acc[im][in][3])
                        : "r"(ah[im][0]), "r"(ah[im][1]), "r"(ah[im][2]), "r"(ah[im][3]),
                          "r"(bh[in][0]), "r"(bh[in][1]));
                }
        }
        __syncthreads();
    }

    // ---- epilogue ----
#pragma unroll
    for (int im = 0; im < MAT; im++) {
        int r0 = m0 + wm * MW + im * 16 + gid;
        int r1 = r0 + 8;
#pragma unroll
        for (int in = 0; in < NAT; in++) {
            int cc = n0 + wn * NW + in * 8 + tig * 2;
            float v0 = acc[im][in][0], v1 = acc[im][in][1];
            float v2 = acc[im][in][2], v3 = acc[im][in][3];
            if (C2) {
                float2 b2 = *(const float2*)&bias2[cc];
                if (r0 < M) *(float2*)&C2[(long long)r0 * N + cc] = make_float2(v0 + b2.x, v1 + b2.y);
                if (r1 < M) *(float2*)&C2[(long long)r1 * N + cc] = make_float2(v2 + b2.x, v3 + b2.y);
            }
            if (bias) {
                float2 bv = *(const float2*)&bias[cc];
                v0 += bv.x; v1 += bv.y; v2 += bv.x; v3 += bv.y;
            }
            if (reluOut) {
                v0 = fmaxf(v0, 0.f); v1 = fmaxf(v1, 0.f);
                v2 = fmaxf(v2, 0.f); v3 = fmaxf(v3, 0.f);
            }
            if (r0 < M) *(float2*)&C[(long long)r0 * N + cc] = make_float2(v0, v1);
            if (r1 < M) *(float2*)&C[(long long)r1 * N + cc] = make_float2(v2, v3);
        }
    }
}

// ---------------- edge scatter: A[dst] += Y[src] (round-1 proven path) ----------------
__global__ void scatter_add(const float* __restrict__ Y, float* __restrict__ A,
                            const void* __restrict__ eidx, int E, int C4) {
    const int is64 = g_is64;
    long long i = (long long)blockIdx.x * blockDim.x + threadIdx.x;
    long long total = (long long)E * C4;
    if (i >= total) return;
    int e = (int)(i / C4);
    int c = (int)(i % C4) * 4;
    int C = C4 * 4;
    int src = load_idx(eidx, e, is64);
    int dst = load_idx(eidx, (long long)E + e, is64);
    float4 v = *(const float4*)&Y[(long long)src * C + c];
    float* p = &A[(long long)dst * C + c];
    atomicAdd(p + 0, v.x);
    atomicAdd(p + 1, v.y);
    atomicAdd(p + 2, v.z);
    atomicAdd(p + 3, v.w);
}

// ---------------- batchnorm statistics + apply (round-1 proven path) ----------------
__global__ void zero_f(float* __restrict__ p, int n) {
    int i = blockIdx.x * blockDim.x + threadIdx.x;
    if (i < n) p[i] = 0.f;
}

__global__ void col_stats(const float* __restrict__ H, int M, int C) {
    const int c = threadIdx.x;            // blockDim.x == C
    const int r0 = blockIdx.x * 256;
    const int r1 = min(r0 + 256, M);
    float s = 0.f, q = 0.f;
    for (int r = r0; r < r1; ++r) {
        float v = H[(long long)r * C + c];
        s += v;
        q = fmaf(v, v, q);
    }
    atomicAdd(&g_stats[c], s);
    atomicAdd(&g_stats[256 + c], q);
}

__global__ void bn_apply(float* __restrict__ H, int M, int C,
                         const float* __restrict__ gam, const float* __restrict__ bet) {
    long long i = (long long)blockIdx.x * blockDim.x + threadIdx.x;
    long long total4 = (long long)M * (C / 4);
    if (i >= total4) return;
    int c = (int)(i % (C / 4)) * 4;
    float4 v = *(float4*)&H[i * 4];
    float invN = 1.f / (float)M;
    float* vp = &v.x;
#pragma unroll
    for (int j = 0; j < 4; j++) {
        float mu = g_stats[c + j] * invN;
        float var = fmaf(-mu, mu, g_stats[256 + c + j] * invN);
        float sc = rsqrtf(var + BN_EPS) * gam[c + j];
        vp[j] = fmaf(vp[j] - mu, sc, bet[c + j]);
    }
    *(float4*)&H[i * 4] = v;
}

// ---------------- pooling + head (round-1 proven path) ----------------
__global__ void pool_add(const float* __restrict__ H, float* __restrict__ P,
                         const void* __restrict__ batch, int M) {
    const int is64 = g_is64;
    long long i = (long long)blockIdx.x * blockDim.x + threadIdx.x;
    long long total = (long long)M * 16;      // C=64 -> 16 float4 per node
    if (i >= total) return;
    int node = (int)(i / 16);
    int c = (int)(i % 16) * 4;
    int gph = load_idx(batch, node, is64);
    float4 v = *(const float4*)&H[(long long)node * 64 + c];
    float* p = &P[(long long)gph * 64 + c];
    atomicAdd(p + 0, v.x);
    atomicAdd(p + 1, v.y);
    atomicAdd(p + 2, v.z);
    atomicAdd(p + 3, v.w);
}

__global__ void head_kernel(const float* __restrict__ P,
                            const float* __restrict__ Wf1, const float* __restrict__ bf1,
                            const float* __restrict__ Wf2, const float* __restrict__ bf2,
                            float* __restrict__ out, int G) {
    int g = blockIdx.x * blockDim.x + threadIdx.x;
    if (g >= G) return;
    float acc[16];
#pragma unroll
    for (int j = 0; j < 16; j++) acc[j] = bf1[j];
    const float* p = &P[(long long)g * 64];
    for (int k = 0; k < 64; k++) {
        float pv = p[k];
#pragma unroll
        for (int j = 0; j < 16; j++) acc[j] = fmaf(pv, Wf1[k * 16 + j], acc[j]);
    }
    float o = bf2[0];
#pragma unroll
    for (int j = 0; j < 16; j++) o = fmaf(fmaxf(acc[j], 0.f), Wf2[j], o);
    out[g] = fmaxf(o, 0.f);
}

// ---------------- host launcher ----------------
static void launch_transpose(const float* W, float* Bt, int K, int N) {
    dim3 grid((N + 31) / 32, (K + 31) / 32);
    transpose_w<<<grid, dim3(32, 8)>>>(W, Bt, K, N);
}

template <int BN_, int WM_, int WN_>
static void launch_gemm(const float* A, const float* Bt, float* C,
                        int M, int N, int K, const float* bias,
                        int reluIn, int reluOut, float* C2, const float* bias2) {
    dim3 grid(N / BN_, (M + 127) / 128);
    mma_gemm<BN_, WM_, WN_><<<grid, 256>>>(A, Bt, C, M, N, K, bias, reluIn, reluOut, C2, bias2);
}

extern "C" void kernel_launch(void* const* d_in, const int* in_sizes, int n_in,
                              void* d_out, int out_size) {
    const float* x    = (const float*)d_in[0];
    const void*  eidx = d_in[1];
    const void*  batc = d_in[2];
    const float* W1a = (const float*)d_in[3];  const float* b1a = (const float*)d_in[4];
    const float* W1b = (const float*)d_in[5];  const float* b1b = (const float*)d_in[6];
    const float* g1  = (const float*)d_in[7];  const float* be1 = (const float*)d_in[8];
    const float* W2a = (const float*)d_in[9];  const float* b2a = (const float*)d_in[10];
    const float* W2b = (const float*)d_in[11]; const float* b2b = (const float*)d_in[12];
    const float* g2  = (const float*)d_in[13]; const float* be2 = (const float*)d_in[14];
    const float* W3a = (const float*)d_in[15]; const float* b3a = (const float*)d_in[16];
    const float* W3b = (const float*)d_in[17]; const float* b3b = (const float*)d_in[18];
    const float* g3  = (const float*)d_in[19]; const float* be3 = (const float*)d_in[20];
    const float* Wf1 = (const float*)d_in[21]; const float* bf1 = (const float*)d_in[22];
    const float* Wf2 = (const float*)d_in[23]; const float* bf2 = (const float*)d_in[24];

    float *Y, *A, *H1, *H2, *H3, *P, *ST, *BT;
    cudaGetSymbolAddress((void**)&Y,  g_Y);
    cudaGetSymbolAddress((void**)&A,  g_A);
    cudaGetSymbolAddress((void**)&H1, g_H1);
    cudaGetSymbolAddress((void**)&H2, g_H2);
    cudaGetSymbolAddress((void**)&H3, g_H3);
    cudaGetSymbolAddress((void**)&P,  g_pool);
    cudaGetSymbolAddress((void**)&ST, g_stats);
    cudaGetSymbolAddress((void**)&BT, g_Bt);

    detect_dtype<<<1, 256>>>((const unsigned int*)eidx, 1024);

    const int M = NN;

    // ---- Layer 1: 373 -> 256 ----
    launch_transpose(W1a, BT, 373, 256);
    launch_gemm<128, 2, 4>(x, BT, Y, M, 256, 373, nullptr, 0, 0, A, b1a);
    {
        long long tot = (long long)NE * 64;
        scatter_add<<<(int)((tot + 255) / 256), 256>>>(Y, A, eidx, NE, 64);
    }
    launch_transpose(W1b, BT, 256, 256);
    launch_gemm<128, 2, 4>(A, BT, H1, M, 256, 256, b1b, 1, 1, nullptr, nullptr);
    zero_f<<<2, 256>>>(ST, 512);
    col_stats<<<(M + 255) / 256, 256>>>(H1, M, 256);
    {
        long long tot4 = (long long)M * 64;
        bn_apply<<<(int)((tot4 + 255) / 256), 256>>>(H1, M, 256, g1, be1);
    }

    // ---- Layer 2: 256 -> 128 ----
    launch_transpose(W2a, BT, 256, 128);
    launch_gemm<128, 2, 4>(H1, BT, Y, M, 128, 256, nullptr, 0, 0, A, b2a);
    {
        long long tot = (long long)NE * 32;
        scatter_add<<<(int)((tot + 255) / 256), 256>>>(Y, A, eidx, NE, 32);
    }
    launch_transpose(W2b, BT, 128, 128);
    launch_gemm<128, 2, 4>(A, BT, H2, M, 128, 128, b2b, 1, 1, nullptr, nullptr);
    zero_f<<<2, 256>>>(ST, 512);
    col_stats<<<(M + 255) / 256, 128>>>(H2, M, 128);
    {
        long long tot4 = (long long)M * 32;
        bn_apply<<<(int)((tot4 + 255) / 256), 256>>>(H2, M, 128, g2, be2);
    }

    // ---- Layer 3: 128 -> 64 ----
    launch_transpose(W3a, BT, 128, 64);
    launch_gemm<64, 4, 2>(H2, BT, Y, M, 64, 128, nullptr, 0, 0, A, b3a);
    {
        long long tot = (long long)NE * 16;
        scatter_add<<<(int)((tot + 255) / 256), 256>>>(Y, A, eidx, NE, 16);
    }
    launch_transpose(W3b, BT, 64, 64);
    launch_gemm<64, 4, 2>(A, BT, H3, M, 64, 64, b3b, 1, 1, nullptr, nullptr);
    zero_f<<<2, 256>>>(ST, 512);
    col_stats<<<(M + 255) / 256, 64>>>(H3, M, 64);
    {
        long long tot4 = (long long)M * 16;
        bn_apply<<<(int)((tot4 + 255) / 256), 256>>>(H3, M, 64, g3, be3);
    }

    // ---- Pool + head ----
    zero_f<<<(NG * 64 + 255) / 256, 256>>>(P, NG * 64);
    {
        long long tot = (long long)M * 16;
        pool_add<<<(int)((tot + 255) / 256), 256>>>(H3, P, batc, M);
    }
    head_kernel<<<(NG + 127) / 128, 128>>>(P, Wf1, bf1, Wf2, bf2, (float*)d_out, NG);
}